// round 17
// baseline (speedup 1.0000x reference)
#include <cuda_runtime.h>
#include <cuda_fp16.h>
#include <cstdint>

#define C_DIM 1024
#define CW    512
#define B_SZ  4
#define W_LEN 4096
#define NHD   8
#define KD    64
#define HD    128
#define L2C   4096
#define L3C   6561
#define L3P   6656
#define NBH   (B_SZ*NHD)
#define SCALE 0.125f

__device__ float    g_q   [NBH * L3C * KD];
__device__ float    g_k   [NBH * L3C * KD];
__device__ float    g_v0  [NBH * L3C * HD];
__device__ float    g_wa  [NBH * L3C * HD];
__device__ float    g_wb  [NBH * L3C * HD];
__device__ float    g_attn[5038848];
__device__ float    g_xf  [B_SZ * W_LEN * C_DIM];
__device__ float    g_x1  [B_SZ * W_LEN * C_DIM];
__device__ uint32_t g_xh  [B_SZ * W_LEN * CW];
__device__ uint32_t g_x1h [B_SZ * L3P  * CW];
__device__ uint32_t g_wp  [2048 * CW];

__device__ __forceinline__ int wordpos(int c) {
    int kb = c >> 6, hk = c & 63;
    int ks = hk >> 4, rem = hk & 15;
    int r = rem >> 3, q = (rem & 7) >> 1;
    return (kb << 5) + (ks << 3) + (q << 1) + r;
}
__device__ __forceinline__ uint32_t pack2(float a, float b) {
    __half2 h = __floats2half2_rn(a, b);
    return *(uint32_t*)&h;
}

// ---------------------------------------------------------------------------
__global__ void conv_w(const float* __restrict__ w0, const float* __restrict__ w1,
                       uint32_t* __restrict__ wp, int rows0, int total)
{
    int idx = blockIdx.x * 256 + threadIdx.x;
    if (idx >= total) return;
    int o = idx >> 9, w = idx & 511;
    int kb = w >> 5, wi = w & 31;
    int ks = wi >> 3, t = wi & 7, q = t >> 1, r = t & 1;
    int hk = (kb << 6) + (ks << 4) + (r << 3) + (q << 1);
    const float* src = (o < rows0) ? (w0 + (size_t)o * C_DIM)
                                   : (w1 + (size_t)(o - rows0) * C_DIM);
    wp[(size_t)o * CW + w] = pack2(src[hk], src[hk + 1]);
}

// ---------------------------------------------------------------------------
__global__ void transpose_x(const float* __restrict__ x,
                            float* __restrict__ xf, uint32_t* __restrict__ xh)
{
    __shared__ float t[32][33];
    const int b = blockIdx.z, l0 = blockIdx.x * 32, c0 = blockIdx.y * 32;
    const int tx = threadIdx.x, ty = threadIdx.y;
    const int tid = ty * 32 + tx;
    #pragma unroll
    for (int j = 0; j < 4; j++)
        t[ty + 8*j][tx] = x[((size_t)b * C_DIM + c0 + ty + 8*j) * W_LEN + l0 + tx];
    __syncthreads();
    #pragma unroll
    for (int j = 0; j < 4; j++) {
        int l = l0 + ty + 8*j;
        xf[((size_t)b * W_LEN + l) * C_DIM + c0 + tx] = t[tx][ty + 8*j];
    }
    for (int i = tid; i < 32 * 16; i += 256) {
        int li = i >> 4, p = i & 15;
        int c = c0 + 2 * p;
        int w = wordpos(c);
        xh[((size_t)b * W_LEN + l0 + li) * CW + w] = pack2(t[2*p][li], t[2*p+1][li]);
    }
}

// ---------------------------------------------------------------------------
// fp16 mma.sync m16n8k16 GEMM (unchanged from R14).
// ---------------------------------------------------------------------------
template<int MODE>
__launch_bounds__(256)
__global__ void gemm_tc(const uint32_t* __restrict__ xh, int Lpad,
                        const uint32_t* __restrict__ wp,
                        const float* __restrict__ s0, const float* __restrict__ b0,
                        const float* __restrict__ s1, const float* __restrict__ b1,
                        float* __restrict__ qbuf, float* __restrict__ kbuf,
                        float* __restrict__ vbuf, int L, int WV)
{
    extern __shared__ float smf[];
    uint32_t* sm = (uint32_t*)smf;
    constexpr int STR = 40;
    uint32_t* Asm[2] = { sm,         sm + 10240 };
    uint32_t* Bsm[2] = { sm + 20480, sm + 25600 };

    const int tid  = threadIdx.x;
    const int lane = tid & 31, warp = tid >> 5;
    const int wm = warp >> 1, wn = warp & 1;
    const int grp = lane >> 2, qid = lane & 3;
    const int l0 = blockIdx.x * 128, o0 = blockIdx.y * 256, bz = blockIdx.z;

    const bool alt = (MODE == 0) && (o0 >= 1024);
    const float* sptr = alt ? (s1 + (o0 - 1024)) : (s0 + o0);
    const float* bptr = alt ? (b1 + (o0 - 1024)) : (b0 + o0);

    if (MODE == 0 && l0 >= WV) {
        for (int f = tid; f < 8192; f += 256) {
            int l = f >> 6, o4 = (f & 63) << 2;
            int lgl = l0 + l;
            if (lgl >= L) continue;
            float4 r = *(const float4*)(bptr + o4);
            int og = o0 + o4;
            float* dst;
            if (o0 < 1024) {
                int h = og >> 7, rr = (og >> 6) & 1, d0 = og & 63;
                dst = (rr ? kbuf : qbuf) + ((size_t)(bz * NHD + h) * L + lgl) * KD + d0;
            } else {
                int oc = og - 1024, h = oc >> 7, d0 = oc & 127;
                dst = vbuf + ((size_t)(bz * NHD + h) * L + lgl) * HD + d0;
            }
            *(float4*)dst = r;
        }
        return;
    }

    const int am = tid >> 3, ak = (tid & 7) * 4;
    const uint32_t* arow = wp + (size_t)(o0 + am) * CW + ak;
    const uint32_t* brow = xh + ((size_t)bz * Lpad + l0 + am) * CW + ak;

    float acc[4][8][4] = {};

    auto load_tile = [&](int buf, int c0w) {
        #pragma unroll
        for (int i = 0; i < 8; i++) {
            uint32_t d = (uint32_t)__cvta_generic_to_shared(&Asm[buf][(am + 32*i) * STR + ak]);
            const uint32_t* s = arow + (size_t)(32*i) * CW + c0w;
            asm volatile("cp.async.ca.shared.global [%0], [%1], 16;\n" :: "r"(d), "l"(s));
        }
        #pragma unroll
        for (int i = 0; i < 4; i++) {
            uint32_t d = (uint32_t)__cvta_generic_to_shared(&Bsm[buf][(am + 32*i) * STR + ak]);
            const uint32_t* s = brow + (size_t)(32*i) * CW + c0w;
            asm volatile("cp.async.ca.shared.global [%0], [%1], 16;\n" :: "r"(d), "l"(s));
        }
        asm volatile("cp.async.commit_group;\n");
    };

    load_tile(0, 0);
    for (int kt = 0; kt < 16; ++kt) {
        asm volatile("cp.async.wait_group 0;\n");
        __syncthreads();
        if (kt + 1 < 16) load_tile((kt + 1) & 1, (kt + 1) * 32);
        const uint32_t* Ab = Asm[kt & 1];
        const uint32_t* Bb = Bsm[kt & 1];

        #pragma unroll
        for (int ks = 0; ks < 4; ++ks) {
            uint32_t bf[8][2];
            #pragma unroll
            for (int nt = 0; nt < 8; ++nt) {
                uint2 bb = *(const uint2*)&Bb[(wn*64 + nt*8 + grp) * STR + ks*8 + qid*2];
                bf[nt][0] = bb.x; bf[nt][1] = bb.y;
            }
            #pragma unroll
            for (int mt = 0; mt < 4; ++mt) {
                const int base = (wm*64 + mt*16 + grp) * STR + ks*8 + qid*2;
                uint2 lo = *(const uint2*)&Ab[base];
                uint2 hi = *(const uint2*)&Ab[base + 8*STR];
                #pragma unroll
                for (int nt = 0; nt < 8; ++nt) {
                    float* d = acc[mt][nt];
                    asm volatile(
                        "mma.sync.aligned.m16n8k16.row.col.f32.f16.f16.f32 "
                        "{%0,%1,%2,%3},{%4,%5,%6,%7},{%8,%9},{%0,%1,%2,%3};\n"
                        : "+f"(d[0]), "+f"(d[1]), "+f"(d[2]), "+f"(d[3])
                        : "r"(lo.x), "r"(hi.x), "r"(lo.y), "r"(hi.y),
                          "r"(bf[nt][0]), "r"(bf[nt][1]));
                }
            }
        }
        __syncthreads();
    }

    float* ep = smf;
    constexpr int EPS = (MODE == 0) ? 260 : 132;
    #pragma unroll
    for (int mt = 0; mt < 4; ++mt)
        #pragma unroll
        for (int nt = 0; nt < 8; ++nt) {
            int ol = wm*64 + mt*16 + grp;
            int ll = wn*64 + nt*8 + 2*qid;
            float* c = acc[mt][nt];
            if (MODE == 0) {
                ep[ll * EPS + ol]           = c[0];
                ep[(ll + 1) * EPS + ol]     = c[1];
                ep[ll * EPS + ol + 8]       = c[2];
                ep[(ll + 1) * EPS + ol + 8] = c[3];
            } else {
                ep[ol * EPS + ll]           = c[0];
                ep[ol * EPS + ll + 1]       = c[1];
                ep[(ol + 8) * EPS + ll]     = c[2];
                ep[(ol + 8) * EPS + ll + 1] = c[3];
            }
        }
    __syncthreads();

    if (MODE == 0) {
        for (int f = tid; f < 8192; f += 256) {
            int l = f >> 6, o4 = (f & 63) << 2;
            int lgl = l0 + l;
            if (lgl >= L) continue;
            float4 v  = *(float4*)&ep[l * EPS + o4];
            float4 s4 = *(const float4*)(sptr + o4);
            float4 b4 = *(const float4*)(bptr + o4);
            float4 r = make_float4(v.x*s4.x + b4.x, v.y*s4.y + b4.y,
                                   v.z*s4.z + b4.z, v.w*s4.w + b4.w);
            int og = o0 + o4;
            float* dst;
            if (o0 < 1024) {
                int h = og >> 7, rr = (og >> 6) & 1, d0 = og & 63;
                dst = (rr ? kbuf : qbuf) + ((size_t)(bz * NHD + h) * L + lgl) * KD + d0;
            } else {
                int oc = og - 1024, h = oc >> 7, d0 = oc & 127;
                dst = vbuf + ((size_t)(bz * NHD + h) * L + lgl) * HD + d0;
            }
            *(float4*)dst = r;
        }
    } else {
        for (int f = tid; f < 8192; f += 256) {
            int o = f >> 5, l4 = (f & 31) << 2;
            float4 v = *(float4*)&ep[o * EPS + l4];
            float sc = sptr[o], bi = bptr[o];
            float4 r = make_float4(v.x*sc + bi, v.y*sc + bi, v.z*sc + bi, v.w*sc + bi);
            *(float4*)(qbuf + ((size_t)(bz * C_DIM + o0 + o)) * W_LEN + l0 + l4) = r;
        }
    }
}

// ---------------------------------------------------------------------------
// FUSED attention + first stage pass.
// INNER=true : inner levels, ASC order, v0 -> wa   (v1's first half)
// INNER=false: outer levels, DESC order, v0 -> wb  (v2's first half)
// ---------------------------------------------------------------------------
template<int BASE, int T, int NE, bool INNER>
__launch_bounds__(256)
__global__ void attn_apply(const float* __restrict__ q, const float* __restrict__ k,
                           const float* __restrict__ vin, float* __restrict__ vout,
                           float* __restrict__ attn, int L)
{
    constexpr int GT = T / BASE;
    constexpr int BB = BASE * BASE;
    constexpr int QSTR = KD + 4;
    extern __shared__ float sh[];
    float* qs = sh;
    float* ks = qs + T * QSTR;
    float* vs = ks + T * QSTR;
    float* ls = vs + T * HD;
    const int tile = blockIdx.x, bh = blockIdx.y, tid = threadIdx.x;

    for (int i = tid; i < T * (KD/4); i += 256) {
        int p = i >> 4, dq = i & 15;
        size_t gb;
        if (INNER) gb = ((size_t)bh * L + (size_t)tile * T + p) * KD;
        else       gb = ((size_t)bh * L + (size_t)p * T + tile) * KD;
        *(float4*)(qs + p * QSTR + dq * 4) = *((const float4*)(q + gb) + dq);
        *(float4*)(ks + p * QSTR + dq * 4) = *((const float4*)(k + gb) + dq);
    }
    if (INNER) {
        size_t gb = ((size_t)bh * L + (size_t)tile * T) * HD;
        const float4* v4 = (const float4*)(vin + gb);
        for (int i = tid; i < T * 32; i += 256) ((float4*)vs)[i] = v4[i];
    } else {
        for (int i = tid; i < T * 32; i += 256) {
            int p = i >> 5, dq = i & 31;
            ((float4*)vs)[i] = *((const float4*)(vin + ((size_t)bh * L + (size_t)p * T + tile) * HD) + dq);
        }
    }
    __syncthreads();

    float4* vs4 = (float4*)vs;
    #pragma unroll
    for (int step = 0; step < NE; step++) {
        const int e = INNER ? step : (NE - 1 - step);
        int s = 1;
        #pragma unroll
        for (int t2 = 0; t2 < NE; t2++) if (t2 < e) s *= BASE;

        for (int it = tid; it < GT * BB; it += 256) {
            int g = it / BB, rem = it % BB;
            int J = rem / BASE, j = rem % BASE;
            int hi = g / s, lo = g % s;
            int pJ = hi * BASE * s + J * s + lo;
            int pj = hi * BASE * s + j * s + lo;
            const float4* qp = (const float4*)(qs + pj * QSTR);
            const float4* kp = (const float4*)(ks + pJ * QSTR);
            float dot = 0.f;
            #pragma unroll
            for (int dd = 0; dd < KD/4; dd++) {
                float4 a = qp[dd], b2 = kp[dd];
                dot += a.x*b2.x + a.y*b2.y + a.z*b2.z + a.w*b2.w;
            }
            ls[it] = dot * SCALE;
        }
        __syncthreads();

        const int eg = e + (INNER ? 0 : NE);
        size_t lvl = ((size_t)eg * NBH + bh) * (size_t)(L / BASE) * BB;
        for (int it = tid; it < GT * BASE; it += 256) {
            int g = it / BASE, J = it % BASE;
            float* lg2 = ls + (g * BASE + J) * BASE;
            float m = lg2[0];
            #pragma unroll
            for (int j = 1; j < BASE; j++) m = fmaxf(m, lg2[j]);
            float ex[BASE]; float sum = 0.f;
            #pragma unroll
            for (int j = 0; j < BASE; j++) { ex[j] = __expf(lg2[j] - m); sum += ex[j]; }
            float inv = 1.f / sum;
            size_t gg = INNER ? ((size_t)tile * GT + g) : ((size_t)g * T + tile);
            float* ap = attn + lvl + gg * BB + (size_t)J * BASE;
            #pragma unroll
            for (int j = 0; j < BASE; j++) {
                float pv = ex[j] * inv;
                lg2[j] = pv;
                ap[j]  = pv;
            }
        }
        __syncthreads();

        for (int w = tid; w < GT * 32; w += 256) {
            int g = w >> 5, d = w & 31;
            int hi = g / s, lo = g - hi * s;
            int pb = hi * BASE * s + lo;
            float4 vv[BASE];
            #pragma unroll
            for (int j = 0; j < BASE; j++) vv[j] = vs4[(pb + j * s) * 32 + d];
            const float* ag = ls + g * BB;
            #pragma unroll
            for (int J = 0; J < BASE; J++) {
                float4 o = make_float4(0.f, 0.f, 0.f, 0.f);
                #pragma unroll
                for (int j = 0; j < BASE; j++) {
                    float a = ag[J * BASE + j];
                    o.x += a * vv[j].x; o.y += a * vv[j].y;
                    o.z += a * vv[j].z; o.w += a * vv[j].w;
                }
                vs4[(pb + J * s) * 32 + d] = o;
            }
        }
        __syncthreads();
    }

    if (INNER) {
        size_t gb = ((size_t)bh * L + (size_t)tile * T) * HD;
        float4* v4 = (float4*)(vout + gb);
        for (int i = tid; i < T * 32; i += 256) v4[i] = ((float4*)vs)[i];
    } else {
        for (int i = tid; i < T * 32; i += 256) {
            int p = i >> 5, dq = i & 31;
            *((float4*)(vout + ((size_t)bh * L + (size_t)p * T + tile) * HD) + dq) = ((float4*)vs)[i];
        }
    }
}

// ---------------------------------------------------------------------------
// Remaining standalone stage pass (outer-asc on wa), float4 apply.
// ---------------------------------------------------------------------------
template<int BASE, int T, int NE, bool INNER, bool ASC>
__launch_bounds__(256)
__global__ void stage_kernel(const float* __restrict__ vin, float* __restrict__ vout,
                             const float* __restrict__ attn, int L)
{
    constexpr int GT = T / BASE;
    constexpr int BB = BASE * BASE;
    __shared__ float vs[T * HD];
    __shared__ float as_[GT * BB];
    const int tile = blockIdx.x, bh = blockIdx.y, tid = threadIdx.x;

    if (INNER) {
        size_t gb = ((size_t)bh * L + (size_t)tile * T) * HD;
        const float4* v4 = (const float4*)(vin + gb);
        for (int i = tid; i < T * 32; i += 256) ((float4*)vs)[i] = v4[i];
    } else {
        for (int i = tid; i < T * 32; i += 256) {
            int p = i >> 5, dq = i & 31;
            ((float4*)vs)[i] = *((const float4*)(vin + ((size_t)bh * L + (size_t)p * T + tile) * HD) + dq);
        }
    }
    __syncthreads();

    float4* vs4 = (float4*)vs;
    #pragma unroll
    for (int step = 0; step < NE; step++) {
        const int e = ASC ? step : (NE - 1 - step);
        int s = 1;
        #pragma unroll
        for (int t2 = 0; t2 < NE; t2++) if (t2 < e) s *= BASE;
        const int eg = e + (INNER ? 0 : NE);
        size_t lvl = ((size_t)eg * NBH + bh) * (size_t)(L / BASE) * BB;
        for (int it = tid; it < GT * BB; it += 256) {
            int g = it / BB, c = it % BB;
            size_t gg = INNER ? ((size_t)tile * GT + g) : ((size_t)g * T + tile);
            as_[it] = attn[lvl + gg * BB + c];
        }
        __syncthreads();
        for (int w = tid; w < GT * 32; w += 256) {
            int g = w >> 5, d = w & 31;
            int hi = g / s, lo = g - hi * s;
            int pb = hi * BASE * s + lo;
            float4 vv[BASE];
            #pragma unroll
            for (int j = 0; j < BASE; j++) vv[j] = vs4[(pb + j * s) * 32 + d];
            const float* ag = as_ + g * BB;
            #pragma unroll
            for (int J = 0; J < BASE; J++) {
                float4 o = make_float4(0.f, 0.f, 0.f, 0.f);
                #pragma unroll
                for (int j = 0; j < BASE; j++) {
                    float a = ag[J * BASE + j];
                    o.x += a * vv[j].x; o.y += a * vv[j].y;
                    o.z += a * vv[j].z; o.w += a * vv[j].w;
                }
                vs4[(pb + J * s) * 32 + d] = o;
            }
        }
        __syncthreads();
    }

    if (INNER) {
        size_t gb = ((size_t)bh * L + (size_t)tile * T) * HD;
        float4* v4 = (float4*)(vout + gb);
        for (int i = tid; i < T * 32; i += 256) v4[i] = ((float4*)vs)[i];
    } else {
        for (int i = tid; i < T * 32; i += 256) {
            int p = i >> 5, dq = i & 31;
            *((float4*)(vout + ((size_t)bh * L + (size_t)p * T + tile) * HD) + dq) = ((float4*)vs)[i];
        }
    }
}

// ---------------------------------------------------------------------------
// FUSED: v2's final inner-desc stage pass + combine; fp16-pair output.
// ---------------------------------------------------------------------------
template<int BASE, int T, int NE>
__launch_bounds__(256)
__global__ void stage_combine(const float* __restrict__ vin,
                              const float* __restrict__ wa,
                              const float* __restrict__ v0,
                              const float* __restrict__ attn,
                              const float* __restrict__ xres, int XRW,
                              const float* __restrict__ wpe, const float* __restrict__ spe,
                              const float* __restrict__ bpe,
                              float* __restrict__ yf, int YFW,
                              uint32_t* __restrict__ yh, int YHW,
                              int L, int WV)
{
    constexpr int GT = T / BASE;
    constexpr int BB = BASE * BASE;
    constexpr int HD2 = HD / 2;
    extern __shared__ float sh[];
    float* vs  = sh;
    float* v0s = sh + T * HD;
    float* prm = v0s + (T + 2) * HD;
    float* as_ = prm + 5 * 128;

    const int tile = blockIdx.x, bh = blockIdx.y, tid = threadIdx.x;
    const int b = bh >> 3, h = bh & 7;

    {
        size_t gb = ((size_t)bh * L + (size_t)tile * T) * HD;
        const float4* v4 = (const float4*)(vin + gb);
        for (int i = tid; i < T * HD / 4; i += 256) ((float4*)vs)[i] = v4[i];
    }
    for (int i = tid; i < (T + 2) * (HD/4); i += 256) {
        int l = i >> 5, dq = i & 31;
        int lg = tile * T - 1 + l;
        float4 v = (lg >= 0 && lg < L)
            ? *((const float4*)(v0 + ((size_t)bh * L + lg) * HD) + dq)
            : make_float4(0.f, 0.f, 0.f, 0.f);
        ((float4*)v0s)[l * 32 + dq] = v;
    }
    if (tid < 128) {
        int c = h * HD + tid;
        prm[tid]       = wpe[c*3];
        prm[128 + tid] = wpe[c*3+1];
        prm[256 + tid] = wpe[c*3+2];
        prm[384 + tid] = spe[c];
        prm[512 + tid] = bpe[c];
    }
    __syncthreads();

    float2* vs2 = (float2*)vs;
    #pragma unroll
    for (int step = 0; step < NE; step++) {
        const int e = NE - 1 - step;
        int s = 1;
        #pragma unroll
        for (int t2 = 0; t2 < NE; t2++) if (t2 < e) s *= BASE;
        size_t lvl = ((size_t)e * NBH + bh) * (size_t)(L / BASE) * BB;
        for (int it = tid; it < GT * BB; it += 256) {
            int g = it / BB, c = it % BB;
            as_[it] = attn[lvl + ((size_t)tile * GT + g) * BB + c];
        }
        __syncthreads();
        for (int w = tid; w < GT * HD2; w += 256) {
            int g = w >> 6, d = w & 63;
            int hi = g / s, lo = g - hi * s;
            int pb = hi * BASE * s + lo;
            float2 vv[BASE];
            #pragma unroll
            for (int j = 0; j < BASE; j++) vv[j] = vs2[(pb + j * s) * HD2 + d];
            const float* ag = as_ + g * BB;
            #pragma unroll
            for (int J = 0; J < BASE; J++) {
                float2 o = make_float2(0.f, 0.f);
                #pragma unroll
                for (int j = 0; j < BASE; j++) {
                    float a = ag[J * BASE + j];
                    o.x += a * vv[j].x;
                    o.y += a * vv[j].y;
                }
                vs2[(pb + J * s) * HD2 + d] = o;
            }
        }
        __syncthreads();
    }

    const bool wf = (yf != nullptr);
    for (int i = tid; i < T * HD2; i += 256) {
        int l = i >> 6, dp = i & 63;
        int gl = tile * T + l;
        if (gl >= WV) continue;
        int d0 = 2 * dp;
        float val[2];
        #pragma unroll
        for (int u = 0; u < 2; u++) {
            int d = d0 + u;
            float pe = (prm[d] * v0s[l * HD + d] + prm[128 + d] * v0s[(l + 1) * HD + d]
                      + prm[256 + d] * v0s[(l + 2) * HD + d]) * prm[384 + d] + prm[512 + d];
            int c = h * HD + d;
            val[u] = xres[((size_t)b * XRW + gl) * C_DIM + c]
                   + vs[l * HD + d]
                   + wa[((size_t)bh * L + gl) * HD + d]
                   + pe;
        }
        int c0 = h * HD + d0;
        if (wf) *(float2*)&yf[((size_t)b * YFW + gl) * C_DIM + c0] = make_float2(val[0], val[1]);
        yh[((size_t)b * YHW + gl) * CW + wordpos(c0)] = pack2(val[0], val[1]);
    }
}

// ---------------------------------------------------------------------------
extern "C" void kernel_launch(void* const* d_in, const int* in_sizes, int n_in,
                              void* d_out, int out_size)
{
    const float* x = (const float*)d_in[0];
    const float *wqk2=(const float*)d_in[1], *sqk2=(const float*)d_in[2], *bqk2=(const float*)d_in[3];
    const float *wv2 =(const float*)d_in[4], *sv2 =(const float*)d_in[5], *bv2 =(const float*)d_in[6];
    const float *wpe2=(const float*)d_in[7], *spe2=(const float*)d_in[8], *bpe2=(const float*)d_in[9];
    const float *wqk3=(const float*)d_in[10],*sqk3=(const float*)d_in[11],*bqk3=(const float*)d_in[12];
    const float *wv3 =(const float*)d_in[13],*sv3 =(const float*)d_in[14],*bv3 =(const float*)d_in[15];
    const float *wpe3=(const float*)d_in[16],*spe3=(const float*)d_in[17],*bpe3=(const float*)d_in[18];
    const float *wproj=(const float*)d_in[19],*sproj=(const float*)d_in[20],*bproj=(const float*)d_in[21];
    float* out = (float*)d_out;

    float *q, *k, *v0, *wa, *wb, *attn, *x1, *xf;
    uint32_t *xh, *x1h, *wp;
    cudaGetSymbolAddress((void**)&q,    g_q);
    cudaGetSymbolAddress((void**)&k,    g_k);
    cudaGetSymbolAddress((void**)&v0,   g_v0);
    cudaGetSymbolAddress((void**)&wa,   g_wa);
    cudaGetSymbolAddress((void**)&wb,   g_wb);
    cudaGetSymbolAddress((void**)&attn, g_attn);
    cudaGetSymbolAddress((void**)&x1,   g_x1);
    cudaGetSymbolAddress((void**)&xf,   g_xf);
    cudaGetSymbolAddress((void**)&xh,   g_xh);
    cudaGetSymbolAddress((void**)&x1h,  g_x1h);
    cudaGetSymbolAddress((void**)&wp,   g_wp);

    const int SMEM = 135168;
    cudaFuncSetAttribute(gemm_tc<0>, cudaFuncAttributeMaxDynamicSharedMemorySize, SMEM);
    cudaFuncSetAttribute(gemm_tc<1>, cudaFuncAttributeMaxDynamicSharedMemorySize, SMEM);
    // qs/ks: T*(KD+4), vs: T*HD, ls: GT*BB   (floats)
    const int AP2 = (64*68*2 + 64*128 + 32*4) * 4;     // 68096 B
    const int AP3 = (81*68*2 + 81*128 + 27*9) * 4;     // 86508 B
    cudaFuncSetAttribute(attn_apply<2,64,6,true >, cudaFuncAttributeMaxDynamicSharedMemorySize, AP2);
    cudaFuncSetAttribute(attn_apply<2,64,6,false>, cudaFuncAttributeMaxDynamicSharedMemorySize, AP2);
    cudaFuncSetAttribute(attn_apply<3,81,4,true >, cudaFuncAttributeMaxDynamicSharedMemorySize, AP3);
    cudaFuncSetAttribute(attn_apply<3,81,4,false>, cudaFuncAttributeMaxDynamicSharedMemorySize, AP3);
    const int SC2 = (64*128 + 66*128 + 5*128 + 32*4) * 4;
    const int SC3 = (81*128 + 83*128 + 5*128 + 27*9) * 4;
    cudaFuncSetAttribute(stage_combine<2,64,6>, cudaFuncAttributeMaxDynamicSharedMemorySize, SC2);
    cudaFuncSetAttribute(stage_combine<3,81,4>, cudaFuncAttributeMaxDynamicSharedMemorySize, SC3);

    transpose_x<<<dim3(128, 32, 4), dim3(32, 8)>>>(x, xf, xh);

    // ---- block 1: base=2, L=4096, NE=6, T=64 ----
    {
        const int L = L2C;
        conv_w<<<(2048 * CW) / 256, 256>>>(wqk2, wv2, wp, 1024, 2048 * CW);
        gemm_tc<0><<<dim3(32,8,4),256,SMEM>>>(xh, W_LEN, wp, sqk2,bqk2, sv2,bv2, q,k,v0, L, W_LEN);
        attn_apply<2,64,6,true ><<<dim3(64,NBH),256,AP2>>>(q,k,v0,wa,attn,L);
        attn_apply<2,64,6,false><<<dim3(64,NBH),256,AP2>>>(q,k,v0,wb,attn,L);
        stage_kernel<2,64,6,false,true><<<dim3(64,NBH),256>>>(wa,wa,attn,L);
        stage_combine<2,64,6><<<dim3(64,NBH),256,SC2>>>(wb, wa, v0, attn,
            xf, W_LEN, wpe2,spe2,bpe2, x1, W_LEN, x1h, L3P, L, L);
    }
    // ---- block 2: base=3, L=6561, NE=4, T=81 ----
    {
        const int L = L3C;
        conv_w<<<(2048 * CW) / 256, 256>>>(wqk3, wv3, wp, 1024, 2048 * CW);
        gemm_tc<0><<<dim3(52,8,4),256,SMEM>>>(x1h, L3P, wp, sqk3,bqk3, sv3,bv3, q,k,v0, L, W_LEN);
        attn_apply<3,81,4,true ><<<dim3(81,NBH),256,AP3>>>(q,k,v0,wa,attn,L);
        attn_apply<3,81,4,false><<<dim3(81,NBH),256,AP3>>>(q,k,v0,wb,attn,L);
        stage_kernel<3,81,4,false,true><<<dim3(81,NBH),256>>>(wa,wa,attn,L);
        stage_combine<3,81,4><<<dim3(81,NBH),256,SC3>>>(wb, wa, v0, attn,
            x1, W_LEN, wpe3,spe3,bpe3, nullptr, 0, xh, W_LEN, L, W_LEN);
    }
    // ---- final projection ----
    conv_w<<<(1024 * CW) / 256, 256>>>(wproj, nullptr, wp, 1024, 1024 * CW);
    gemm_tc<1><<<dim3(32,4,4),256,SMEM>>>(xh, W_LEN, wp, sproj,bproj, nullptr,nullptr,
                                          out, nullptr, nullptr, W_LEN, W_LEN);
}